// round 1
// baseline (speedup 1.0000x reference)
#include <cuda_runtime.h>
#include <cuda_bf16.h>
#include <math.h>

// Problem constants (fixed by reference)
#define NNODES 100000
#define DFEAT  128
#define EMAX   1600000
#define ALPHA_C 0.1f

// ---------------- scratch (device globals; no allocation allowed) ----------------
__device__ float  g_h1[NNODES * DFEAT];
__device__ float  g_h2[NNODES * DFEAT];
__device__ float  g_feat1[NNODES * DFEAT];
__device__ float  g_feat2[NNODES * DFEAT];
__device__ int    g_col1[EMAX];
__device__ int    g_col2[EMAX];
__device__ int    g_deg1[NNODES];
__device__ int    g_deg2[NNODES];
__device__ int    g_rowptr1[NNODES + 1];
__device__ int    g_rowptr2[NNODES + 1];
__device__ int    g_cursor1[NNODES];
__device__ int    g_cursor2[NNODES];
__device__ float  g_norm1[NNODES];
__device__ float  g_norm2[NNODES];
__device__ double g_sum[256];    // [graph*128 + col]
__device__ double g_sumsq[256];
__device__ float  g_mean[256];
__device__ float  g_rstd[256];

// ---------------- kernels ----------------

// zero degree arrays + stats accumulators
__global__ void zero_kernel(int* d1, int* d2, double* s, double* s2, int n) {
    int i = blockIdx.x * blockDim.x + threadIdx.x;
    if (i < n) { d1[i] = 0; d2[i] = 0; }
    if (i < 256) { s[i] = 0.0; s2[i] = 0.0; }
}

// in-degree histogram
__global__ void hist_kernel(const int* __restrict__ dst, int* __restrict__ deg, int E) {
    int i = blockIdx.x * blockDim.x + threadIdx.x;
    if (i < E) atomicAdd(&deg[dst[i]], 1);
}

// single-block chunked scan: rowptr (exclusive), cursor copy, norm = clip(deg,1)^-0.5
__global__ void scan_kernel(const int* __restrict__ deg, int* __restrict__ rowptr,
                            int* __restrict__ cursor, float* __restrict__ norm, int n) {
    __shared__ int sdata[1024];
    __shared__ int carry_s;
    int tid = threadIdx.x;
    if (tid == 0) carry_s = 0;
    __syncthreads();
    for (int base = 0; base < n; base += 1024) {
        int i = base + tid;
        int x = (i < n) ? deg[i] : 0;
        sdata[tid] = x;
        __syncthreads();
        #pragma unroll
        for (int off = 1; off < 1024; off <<= 1) {
            int v = (tid >= off) ? sdata[tid - off] : 0;
            __syncthreads();
            sdata[tid] += v;
            __syncthreads();
        }
        int incl = sdata[tid];
        int carry = carry_s;
        if (i < n) {
            int excl = carry + incl - x;
            rowptr[i] = excl;
            cursor[i] = excl;
            norm[i] = rsqrtf(fmaxf((float)x, 1.0f));
        }
        __syncthreads();
        if (tid == 1023) carry_s = carry + incl;
        __syncthreads();
    }
    if (tid == 0) rowptr[n] = carry_s;
}

// CSR fill: col list grouped by dst
__global__ void fill_kernel(const int* __restrict__ src, const int* __restrict__ dst,
                            int* __restrict__ cursor, int* __restrict__ col, int E) {
    int i = blockIdx.x * blockDim.x + threadIdx.x;
    if (i < E) {
        int d = dst[i];
        int p = atomicAdd(&cursor[d], 1);
        col[p] = src[i];
    }
}

// warp-per-row aggregation:
// h[i] = (1-ALPHA)*norm[i]*sum_{e in row i} norm[src]*feat[src] + ALPHA*feat0[i]
__global__ __launch_bounds__(256) void aggregate_kernel(
    const float* __restrict__ feat, const float* __restrict__ feat0,
    const float* __restrict__ norm, const int* __restrict__ rowptr,
    const int* __restrict__ col, float* __restrict__ h, int n)
{
    int warp = (blockIdx.x * blockDim.x + threadIdx.x) >> 5;
    int lane = threadIdx.x & 31;
    if (warp >= n) return;
    int e0 = rowptr[warp];
    int e1 = rowptr[warp + 1];
    float4 acc = make_float4(0.f, 0.f, 0.f, 0.f);
    int e = e0;
    for (; e + 1 < e1; e += 2) {
        int s0 = __ldg(&col[e]);
        int s1 = __ldg(&col[e + 1]);
        float n0 = __ldg(&norm[s0]);
        float n1 = __ldg(&norm[s1]);
        float4 f0 = *(const float4*)&feat[s0 * DFEAT + lane * 4];
        float4 f1 = *(const float4*)&feat[s1 * DFEAT + lane * 4];
        acc.x += n0 * f0.x + n1 * f1.x;
        acc.y += n0 * f0.y + n1 * f1.y;
        acc.z += n0 * f0.z + n1 * f1.z;
        acc.w += n0 * f0.w + n1 * f1.w;
    }
    if (e < e1) {
        int s0 = __ldg(&col[e]);
        float n0 = __ldg(&norm[s0]);
        float4 f0 = *(const float4*)&feat[s0 * DFEAT + lane * 4];
        acc.x += n0 * f0.x; acc.y += n0 * f0.y;
        acc.z += n0 * f0.z; acc.w += n0 * f0.w;
    }
    float scale = (1.0f - ALPHA_C) * norm[warp];
    float4 f0v = *(const float4*)&feat0[warp * DFEAT + lane * 4];
    float4 o;
    o.x = scale * acc.x + ALPHA_C * f0v.x;
    o.y = scale * acc.y + ALPHA_C * f0v.y;
    o.z = scale * acc.z + ALPHA_C * f0v.z;
    o.w = scale * acc.w + ALPHA_C * f0v.w;
    *(float4*)&h[warp * DFEAT + lane * 4] = o;
}

// fused fp32 GEMM + GCNII epilogue:
// feat_out = relu((1-beta)*h + beta*(h @ W) + bias)
// tile: 128 rows x 128 cols, BK=32, 256 threads, 8x8 per thread
__global__ __launch_bounds__(256, 2) void gemm_kernel(
    const float* __restrict__ h, const float* __restrict__ W,
    const float* __restrict__ bias, float* __restrict__ out,
    float beta, int nrows)
{
    __shared__ float Hs[32][128];  // [kk][row]
    __shared__ float Ws[32][128];  // [kk][col]
    int block_row = blockIdx.x * 128;
    int tid = threadIdx.x;
    int ty = tid >> 4;      // 0..15 -> rows ty*8..+7
    int tx = tid & 15;      // 0..15 -> cols tx*8..+7
    float acc[8][8];
    #pragma unroll
    for (int u = 0; u < 8; u++)
        #pragma unroll
        for (int v = 0; v < 8; v++) acc[u][v] = 0.f;

    for (int kt = 0; kt < 128; kt += 32) {
        // load H tile (transposed into Hs[kk][row])
        #pragma unroll
        for (int t = tid; t < 1024; t += 256) {
            int row = t >> 3;
            int c4 = t & 7;
            int grow = block_row + row;
            float4 v = make_float4(0.f, 0.f, 0.f, 0.f);
            if (grow < nrows)
                v = *(const float4*)&h[grow * DFEAT + kt + c4 * 4];
            Hs[c4 * 4 + 0][row] = v.x;
            Hs[c4 * 4 + 1][row] = v.y;
            Hs[c4 * 4 + 2][row] = v.z;
            Hs[c4 * 4 + 3][row] = v.w;
        }
        // load W tile (natural layout Ws[kk][col])
        #pragma unroll
        for (int t = tid; t < 1024; t += 256) {
            int kk = t >> 5;
            int c4 = t & 31;
            *(float4*)&Ws[kk][c4 * 4] = *(const float4*)&W[(kt + kk) * DFEAT + c4 * 4];
        }
        __syncthreads();
        #pragma unroll
        for (int kk = 0; kk < 32; kk++) {
            float a[8], b[8];
            *(float4*)&a[0] = *(float4*)&Hs[kk][ty * 8];
            *(float4*)&a[4] = *(float4*)&Hs[kk][ty * 8 + 4];
            *(float4*)&b[0] = *(float4*)&Ws[kk][tx * 8];
            *(float4*)&b[4] = *(float4*)&Ws[kk][tx * 8 + 4];
            #pragma unroll
            for (int u = 0; u < 8; u++)
                #pragma unroll
                for (int v = 0; v < 8; v++)
                    acc[u][v] += a[u] * b[v];
        }
        __syncthreads();
    }

    float omb = 1.0f - beta;
    #pragma unroll
    for (int u = 0; u < 8; u++) {
        int grow = block_row + ty * 8 + u;
        if (grow >= nrows) continue;
        #pragma unroll
        for (int v4 = 0; v4 < 2; v4++) {
            int j = tx * 8 + v4 * 4;
            float4 hv = *(const float4*)&h[grow * DFEAT + j];
            float4 bv = *(const float4*)&bias[j];
            float4 o;
            o.x = fmaxf(omb * hv.x + beta * acc[u][v4 * 4 + 0] + bv.x, 0.f);
            o.y = fmaxf(omb * hv.y + beta * acc[u][v4 * 4 + 1] + bv.y, 0.f);
            o.z = fmaxf(omb * hv.z + beta * acc[u][v4 * 4 + 2] + bv.z, 0.f);
            o.w = fmaxf(omb * hv.w + beta * acc[u][v4 * 4 + 3] + bv.w, 0.f);
            *(float4*)&out[grow * DFEAT + j] = o;
        }
    }
}

// per-column sums / sumsq (double accumulation)
__global__ void colstats_kernel(const float* __restrict__ f, double* __restrict__ sum,
                                double* __restrict__ sumsq, int n) {
    __shared__ double ss[256];
    __shared__ double ss2[256];
    int col = threadIdx.x & 127;
    int half = threadIdx.x >> 7;
    double s = 0.0, s2 = 0.0;
    for (int r = blockIdx.x * 2 + half; r < n; r += gridDim.x * 2) {
        float v = f[r * DFEAT + col];
        s += (double)v;
        s2 += (double)v * (double)v;
    }
    ss[threadIdx.x] = s;
    ss2[threadIdx.x] = s2;
    __syncthreads();
    if (half == 0) {
        atomicAdd(&sum[col], ss[threadIdx.x] + ss[threadIdx.x + 128]);
        atomicAdd(&sumsq[col], ss2[threadIdx.x] + ss2[threadIdx.x + 128]);
    }
}

// mean + 1/clip(std,eps) (ddof=1)
__global__ void finalize_kernel(const double* __restrict__ sum, const double* __restrict__ sumsq,
                                float* __restrict__ mean, float* __restrict__ rstd, int n) {
    int i = threadIdx.x;
    if (i < 256) {
        double s = sum[i], s2 = sumsq[i];
        double m = s / (double)n;
        double var = (s2 - s * s / (double)n) / (double)(n - 1);
        double sd = sqrt(fmax(var, 0.0));
        sd = fmax(sd, 1e-12);
        mean[i] = (float)m;
        rstd[i] = (float)(1.0 / sd);
    }
}

// standardize + write
__global__ void writeout_kernel(const float* __restrict__ f, const float* __restrict__ mean,
                                const float* __restrict__ rstd, float* __restrict__ out, int n) {
    int idx = blockIdx.x * blockDim.x + threadIdx.x;  // over n*32 float4s
    if (idx >= n * 32) return;
    int c4 = idx & 31;
    float4 v = ((const float4*)f)[idx];
    float4 m = ((const float4*)mean)[c4];
    float4 r = ((const float4*)rstd)[c4];
    float4 o;
    o.x = (v.x - m.x) * r.x;
    o.y = (v.y - m.y) * r.y;
    o.z = (v.z - m.z) * r.z;
    o.w = (v.w - m.w) * r.w;
    ((float4*)out)[idx] = o;
}

// ---------------- host launcher ----------------

static void* sym_addr(const void* symbol) {
    void* p = nullptr;
    cudaGetSymbolAddress(&p, symbol);
    return p;
}

extern "C" void kernel_launch(void* const* d_in, const int* in_sizes, int n_in,
                              void* d_out, int out_size) {
    const float* feat1   = (const float*)d_in[0];
    const float* feat2   = (const float*)d_in[1];
    const int*   src1    = (const int*)d_in[2];
    const int*   dst1    = (const int*)d_in[3];
    const int*   src2    = (const int*)d_in[4];
    const int*   dst2    = (const int*)d_in[5];
    const float* weights = (const float*)d_in[6];
    const float* biases  = (const float*)d_in[7];
    const int E1 = in_sizes[2];
    const int E2 = in_sizes[4];
    const int N = NNODES;
    const int L = in_sizes[7] / DFEAT;

    float* p_h1    = (float*)sym_addr(g_h1);
    float* p_h2    = (float*)sym_addr(g_h2);
    float* p_f1    = (float*)sym_addr(g_feat1);
    float* p_f2    = (float*)sym_addr(g_feat2);
    int*   p_col1  = (int*)sym_addr(g_col1);
    int*   p_col2  = (int*)sym_addr(g_col2);
    int*   p_deg1  = (int*)sym_addr(g_deg1);
    int*   p_deg2  = (int*)sym_addr(g_deg2);
    int*   p_rp1   = (int*)sym_addr(g_rowptr1);
    int*   p_rp2   = (int*)sym_addr(g_rowptr2);
    int*   p_cur1  = (int*)sym_addr(g_cursor1);
    int*   p_cur2  = (int*)sym_addr(g_cursor2);
    float* p_norm1 = (float*)sym_addr(g_norm1);
    float* p_norm2 = (float*)sym_addr(g_norm2);
    double* p_sum  = (double*)sym_addr(g_sum);
    double* p_sq   = (double*)sym_addr(g_sumsq);
    float* p_mean  = (float*)sym_addr(g_mean);
    float* p_rstd  = (float*)sym_addr(g_rstd);

    // 1. zero deg + stats
    zero_kernel<<<(N + 255) / 256, 256>>>(p_deg1, p_deg2, p_sum, p_sq, N);

    // 2. degree histograms
    hist_kernel<<<(E1 + 255) / 256, 256>>>(dst1, p_deg1, E1);
    hist_kernel<<<(E2 + 255) / 256, 256>>>(dst2, p_deg2, E2);

    // 3. scan -> rowptr/cursor/norm
    scan_kernel<<<1, 1024>>>(p_deg1, p_rp1, p_cur1, p_norm1, N);
    scan_kernel<<<1, 1024>>>(p_deg2, p_rp2, p_cur2, p_norm2, N);

    // 4. CSR fill
    fill_kernel<<<(E1 + 255) / 256, 256>>>(src1, dst1, p_cur1, p_col1, E1);
    fill_kernel<<<(E2 + 255) / 256, 256>>>(src2, dst2, p_cur2, p_col2, E2);

    // 5. GCNII layers
    const int agg_blocks = (N * 32 + 255) / 256;
    const int gemm_blocks = (N + 127) / 128;
    const float* cur1 = feat1;
    const float* cur2 = feat2;
    for (int l = 0; l < L; l++) {
        float beta = (float)log(1.0 / (double)(l + 1) + 1.0);  // LAMBDA=1
        const float* Wl = weights + (size_t)l * DFEAT * DFEAT;
        const float* bl = biases + (size_t)l * DFEAT;

        aggregate_kernel<<<agg_blocks, 256>>>(cur1, feat1, p_norm1, p_rp1, p_col1, p_h1, N);
        gemm_kernel<<<gemm_blocks, 256>>>(p_h1, Wl, bl, p_f1, beta, N);
        cur1 = p_f1;

        aggregate_kernel<<<agg_blocks, 256>>>(cur2, feat2, p_norm2, p_rp2, p_col2, p_h2, N);
        gemm_kernel<<<gemm_blocks, 256>>>(p_h2, Wl, bl, p_f2, beta, N);
        cur2 = p_f2;
    }

    // 6. column stats
    colstats_kernel<<<256, 256>>>(p_f1, p_sum, p_sq, N);
    colstats_kernel<<<256, 256>>>(p_f2, p_sum + 128, p_sq + 128, N);

    // 7. mean / rstd
    finalize_kernel<<<1, 256>>>(p_sum, p_sq, p_mean, p_rstd, N);

    // 8. standardized output: [h1 | h2]
    float* out = (float*)d_out;
    const int wo_blocks = (N * 32 + 255) / 256;
    writeout_kernel<<<wo_blocks, 256>>>(p_f1, p_mean, p_rstd, out, N);
    writeout_kernel<<<wo_blocks, 256>>>(p_f2, p_mean + 128, p_rstd + 128, out + (size_t)N * DFEAT, N);
}

// round 2
// speedup vs baseline: 1.2662x; 1.2662x over previous
#include <cuda_runtime.h>
#include <cuda_bf16.h>
#include <math.h>

// Problem constants (fixed by reference)
#define NNODES 100000
#define DFEAT  128
#define EMAX   1600000
#define ALPHA_C 0.1f
#define LMAX   8

// ---------------- scratch (device globals; no allocation allowed) ----------------
__device__ float  g_h1[NNODES * DFEAT];
__device__ float  g_h2[NNODES * DFEAT];
__device__ float  g_feat1[NNODES * DFEAT];
__device__ float  g_feat2[NNODES * DFEAT];
__device__ float  g_wp[LMAX * DFEAT * DFEAT];
__device__ int    g_col1[EMAX];
__device__ int    g_col2[EMAX];
__device__ int    g_deg1[NNODES];
__device__ int    g_deg2[NNODES];
__device__ int    g_rowptr1[NNODES + 1];
__device__ int    g_rowptr2[NNODES + 1];
__device__ int    g_cursor1[NNODES];
__device__ int    g_cursor2[NNODES];
__device__ float  g_norm1[NNODES];
__device__ float  g_norm2[NNODES];
__device__ double g_sum[256];    // [graph*128 + col]
__device__ double g_sumsq[256];
__device__ float  g_mean[256];
__device__ float  g_rstd[256];

// ---------------- kernels ----------------

// zero degree arrays + stats accumulators
__global__ void zero_kernel(int* d1, int* d2, double* s, double* s2, int n) {
    int i = blockIdx.x * blockDim.x + threadIdx.x;
    if (i < n) { d1[i] = 0; d2[i] = 0; }
    if (i < 256) { s[i] = 0.0; s2[i] = 0.0; }
}

// in-degree histograms, both graphs (gridDim.y = 2)
__global__ void hist2_kernel(const int* __restrict__ dstA, int* __restrict__ degA, int EA,
                             const int* __restrict__ dstB, int* __restrict__ degB, int EB) {
    const int* dst = blockIdx.y ? dstB : dstA;
    int*       deg = blockIdx.y ? degB : degA;
    int        E   = blockIdx.y ? EB : EA;
    int i = blockIdx.x * blockDim.x + threadIdx.x;
    if (i < E) atomicAdd(&deg[dst[i]], 1);
}

// fast single-block-per-graph scan: 1024 threads, 4 elems/thread, warp-shuffle scan.
// writes rowptr (exclusive), cursor copy, norm = clip(deg,1)^-0.5
__global__ __launch_bounds__(1024) void scan2_kernel(
    const int* __restrict__ degA, int* __restrict__ rpA, int* __restrict__ curA, float* __restrict__ normA,
    const int* __restrict__ degB, int* __restrict__ rpB, int* __restrict__ curB, float* __restrict__ normB,
    int n)
{
    const int* deg  = blockIdx.x ? degB  : degA;
    int*       rp   = blockIdx.x ? rpB   : rpA;
    int*       cur  = blockIdx.x ? curB  : curA;
    float*     norm = blockIdx.x ? normB : normA;

    __shared__ int wsum[32];
    __shared__ int s_carry;
    int tid = threadIdx.x, lane = tid & 31, wid = tid >> 5;
    if (tid == 0) s_carry = 0;
    __syncthreads();

    for (int base = 0; base < n; base += 4096) {
        int idx = base + tid * 4;
        int v0 = (idx + 0 < n) ? deg[idx + 0] : 0;
        int v1 = (idx + 1 < n) ? deg[idx + 1] : 0;
        int v2 = (idx + 2 < n) ? deg[idx + 2] : 0;
        int v3 = (idx + 3 < n) ? deg[idx + 3] : 0;
        int p0 = v0, p1 = p0 + v1, p2 = p1 + v2, p3 = p2 + v3;
        int tot = p3;
        #pragma unroll
        for (int off = 1; off < 32; off <<= 1) {
            int t = __shfl_up_sync(0xFFFFFFFFu, tot, off);
            if (lane >= off) tot += t;
        }
        if (lane == 31) wsum[wid] = tot;
        __syncthreads();
        if (wid == 0) {
            int w = wsum[lane];
            #pragma unroll
            for (int off = 1; off < 32; off <<= 1) {
                int t = __shfl_up_sync(0xFFFFFFFFu, w, off);
                if (lane >= off) w += t;
            }
            wsum[lane] = w;
        }
        __syncthreads();
        int carry = s_carry;
        int excl = carry + (wid ? wsum[wid - 1] : 0) + (tot - p3);
        if (idx + 0 < n) { rp[idx + 0] = excl;      cur[idx + 0] = excl;      norm[idx + 0] = rsqrtf(fmaxf((float)v0, 1.f)); }
        if (idx + 1 < n) { rp[idx + 1] = excl + p0; cur[idx + 1] = excl + p0; norm[idx + 1] = rsqrtf(fmaxf((float)v1, 1.f)); }
        if (idx + 2 < n) { rp[idx + 2] = excl + p1; cur[idx + 2] = excl + p1; norm[idx + 2] = rsqrtf(fmaxf((float)v2, 1.f)); }
        if (idx + 3 < n) { rp[idx + 3] = excl + p2; cur[idx + 3] = excl + p2; norm[idx + 3] = rsqrtf(fmaxf((float)v3, 1.f)); }
        __syncthreads();
        if (tid == 0) s_carry = carry + wsum[31];
        __syncthreads();
    }
    if (tid == 0) rp[n] = s_carry;
}

// CSR fill, both graphs
__global__ void fill2_kernel(const int* __restrict__ srcA, const int* __restrict__ dstA,
                             int* __restrict__ curA, int* __restrict__ colA, int EA,
                             const int* __restrict__ srcB, const int* __restrict__ dstB,
                             int* __restrict__ curB, int* __restrict__ colB, int EB) {
    const int* src = blockIdx.y ? srcB : srcA;
    const int* dst = blockIdx.y ? dstB : dstA;
    int* cursor    = blockIdx.y ? curB : curA;
    int* col       = blockIdx.y ? colB : colA;
    int  E         = blockIdx.y ? EB : EA;
    int i = blockIdx.x * blockDim.x + threadIdx.x;
    if (i < E) {
        int d = dst[i];
        int p = atomicAdd(&cursor[d], 1);
        col[p] = src[i];
    }
}

// W' = (1-beta)*I + beta*W  per layer (gridDim.y = L)
__global__ void wprime_kernel(const float* __restrict__ W, float* __restrict__ Wp) {
    int l = blockIdx.y;
    int i = blockIdx.x * blockDim.x + threadIdx.x;   // 0..16383
    if (i >= DFEAT * DFEAT) return;
    float beta = logf(1.0f / (float)(l + 1) + 1.0f); // LAMBDA = 1
    int r = i >> 7, c = i & 127;
    float v = beta * W[l * DFEAT * DFEAT + i];
    if (r == c) v += 1.0f - beta;
    Wp[l * DFEAT * DFEAT + i] = v;
}

// warp-per-row aggregation, both graphs (gridDim.y = 2):
// h[i] = (1-ALPHA)*norm[i]*sum_{e in row i} norm[src]*feat[src] + ALPHA*feat0[i]
__global__ __launch_bounds__(256) void aggregate2_kernel(
    const float* __restrict__ fA, const float* __restrict__ f0A, const float* __restrict__ nmA,
    const int* __restrict__ rpA, const int* __restrict__ colA, float* __restrict__ hA,
    const float* __restrict__ fB, const float* __restrict__ f0B, const float* __restrict__ nmB,
    const int* __restrict__ rpB, const int* __restrict__ colB, float* __restrict__ hB,
    int n)
{
    const float* feat  = blockIdx.y ? fB  : fA;
    const float* feat0 = blockIdx.y ? f0B : f0A;
    const float* norm  = blockIdx.y ? nmB : nmA;
    const int*   rowptr= blockIdx.y ? rpB : rpA;
    const int*   col   = blockIdx.y ? colB: colA;
    float*       h     = blockIdx.y ? hB  : hA;

    int warp = (blockIdx.x * blockDim.x + threadIdx.x) >> 5;
    int lane = threadIdx.x & 31;
    if (warp >= n) return;
    int e0 = __ldg(&rowptr[warp]);
    int e1 = __ldg(&rowptr[warp + 1]);
    float4 acc = make_float4(0.f, 0.f, 0.f, 0.f);
    int e = e0;
    for (; e + 1 < e1; e += 2) {
        int s0 = __ldg(&col[e]);
        int s1 = __ldg(&col[e + 1]);
        float n0 = __ldg(&norm[s0]);
        float n1 = __ldg(&norm[s1]);
        float4 f0 = __ldg((const float4*)&feat[s0 * DFEAT + lane * 4]);
        float4 f1 = __ldg((const float4*)&feat[s1 * DFEAT + lane * 4]);
        acc.x += n0 * f0.x + n1 * f1.x;
        acc.y += n0 * f0.y + n1 * f1.y;
        acc.z += n0 * f0.z + n1 * f1.z;
        acc.w += n0 * f0.w + n1 * f1.w;
    }
    if (e < e1) {
        int s0 = __ldg(&col[e]);
        float n0 = __ldg(&norm[s0]);
        float4 f0 = __ldg((const float4*)&feat[s0 * DFEAT + lane * 4]);
        acc.x += n0 * f0.x; acc.y += n0 * f0.y;
        acc.z += n0 * f0.z; acc.w += n0 * f0.w;
    }
    float scale = (1.0f - ALPHA_C) * __ldg(&norm[warp]);
    float4 f0v = __ldg((const float4*)&feat0[warp * DFEAT + lane * 4]);
    float4 o;
    o.x = scale * acc.x + ALPHA_C * f0v.x;
    o.y = scale * acc.y + ALPHA_C * f0v.y;
    o.z = scale * acc.z + ALPHA_C * f0v.z;
    o.w = scale * acc.w + ALPHA_C * f0v.w;
    *(float4*)&h[warp * DFEAT + lane * 4] = o;
}

// fused fp32 GEMM + epilogue, both graphs (gridDim.y = 2):
// feat_out = relu(h @ W' + bias)     (identity mapping folded into W')
// tile: 128 rows x 128 cols, BK=32, 256 threads, 8x8 per thread
__global__ __launch_bounds__(256, 2) void gemm2_kernel(
    const float* __restrict__ hA, float* __restrict__ outA,
    const float* __restrict__ hB, float* __restrict__ outB,
    const float* __restrict__ W, const float* __restrict__ bias, int nrows)
{
    const float* h   = blockIdx.y ? hB  : hA;
    float*       out = blockIdx.y ? outB : outA;

    __shared__ float Hs[32][128];  // [kk][row]
    __shared__ float Ws[32][128];  // [kk][col]
    int block_row = blockIdx.x * 128;
    int tid = threadIdx.x;
    int ty = tid >> 4;      // 0..15 -> rows ty*8..+7
    int tx = tid & 15;      // 0..15 -> cols tx*8..+7
    float acc[8][8];
    #pragma unroll
    for (int u = 0; u < 8; u++)
        #pragma unroll
        for (int v = 0; v < 8; v++) acc[u][v] = 0.f;

    for (int kt = 0; kt < 128; kt += 32) {
        // load H tile (transposed into Hs[kk][row])
        #pragma unroll
        for (int t = tid; t < 1024; t += 256) {
            int row = t >> 3;
            int c4 = t & 7;
            int grow = block_row + row;
            float4 v = make_float4(0.f, 0.f, 0.f, 0.f);
            if (grow < nrows)
                v = *(const float4*)&h[grow * DFEAT + kt + c4 * 4];
            Hs[c4 * 4 + 0][row] = v.x;
            Hs[c4 * 4 + 1][row] = v.y;
            Hs[c4 * 4 + 2][row] = v.z;
            Hs[c4 * 4 + 3][row] = v.w;
        }
        // load W tile (natural layout Ws[kk][col])
        #pragma unroll
        for (int t = tid; t < 1024; t += 256) {
            int kk = t >> 5;
            int c4 = t & 31;
            *(float4*)&Ws[kk][c4 * 4] = *(const float4*)&W[(kt + kk) * DFEAT + c4 * 4];
        }
        __syncthreads();
        #pragma unroll
        for (int kk = 0; kk < 32; kk++) {
            float a[8], b[8];
            *(float4*)&a[0] = *(float4*)&Hs[kk][ty * 8];
            *(float4*)&a[4] = *(float4*)&Hs[kk][ty * 8 + 4];
            *(float4*)&b[0] = *(float4*)&Ws[kk][tx * 8];
            *(float4*)&b[4] = *(float4*)&Ws[kk][tx * 8 + 4];
            #pragma unroll
            for (int u = 0; u < 8; u++)
                #pragma unroll
                for (int v = 0; v < 8; v++)
                    acc[u][v] += a[u] * b[v];
        }
        __syncthreads();
    }

    #pragma unroll
    for (int u = 0; u < 8; u++) {
        int grow = block_row + ty * 8 + u;
        if (grow >= nrows) continue;
        #pragma unroll
        for (int v4 = 0; v4 < 2; v4++) {
            int j = tx * 8 + v4 * 4;
            float4 bv = *(const float4*)&bias[j];
            float4 o;
            o.x = fmaxf(acc[u][v4 * 4 + 0] + bv.x, 0.f);
            o.y = fmaxf(acc[u][v4 * 4 + 1] + bv.y, 0.f);
            o.z = fmaxf(acc[u][v4 * 4 + 2] + bv.z, 0.f);
            o.w = fmaxf(acc[u][v4 * 4 + 3] + bv.w, 0.f);
            *(float4*)&out[grow * DFEAT + j] = o;
        }
    }
}

// per-column sums / sumsq (double accumulation), both graphs (gridDim.y = 2)
__global__ void colstats2_kernel(const float* __restrict__ fA, const float* __restrict__ fB,
                                 double* __restrict__ sum, double* __restrict__ sumsq, int n) {
    const float* f = blockIdx.y ? fB : fA;
    int soff = blockIdx.y * 128;
    __shared__ double ss[256];
    __shared__ double ss2[256];
    int col = threadIdx.x & 127;
    int half = threadIdx.x >> 7;
    double s = 0.0, s2 = 0.0;
    for (int r = blockIdx.x * 2 + half; r < n; r += gridDim.x * 2) {
        float v = f[r * DFEAT + col];
        s += (double)v;
        s2 += (double)v * (double)v;
    }
    ss[threadIdx.x] = s;
    ss2[threadIdx.x] = s2;
    __syncthreads();
    if (half == 0) {
        atomicAdd(&sum[soff + col], ss[threadIdx.x] + ss[threadIdx.x + 128]);
        atomicAdd(&sumsq[soff + col], ss2[threadIdx.x] + ss2[threadIdx.x + 128]);
    }
}

// mean + 1/clip(std,eps) (ddof=1)
__global__ void finalize_kernel(const double* __restrict__ sum, const double* __restrict__ sumsq,
                                float* __restrict__ mean, float* __restrict__ rstd, int n) {
    int i = threadIdx.x;
    if (i < 256) {
        double s = sum[i], s2 = sumsq[i];
        double m = s / (double)n;
        double var = (s2 - s * s / (double)n) / (double)(n - 1);
        double sd = sqrt(fmax(var, 0.0));
        sd = fmax(sd, 1e-12);
        mean[i] = (float)m;
        rstd[i] = (float)(1.0 / sd);
    }
}

// standardize + write, both graphs (gridDim.y = 2)
__global__ void writeout2_kernel(const float* __restrict__ fA, const float* __restrict__ fB,
                                 const float* __restrict__ mean, const float* __restrict__ rstd,
                                 float* __restrict__ out, int n) {
    const float* f = blockIdx.y ? fB : fA;
    int soff4 = blockIdx.y * 32;
    float* o_base = out + (size_t)blockIdx.y * n * DFEAT;
    int idx = blockIdx.x * blockDim.x + threadIdx.x;  // over n*32 float4s
    if (idx >= n * 32) return;
    int c4 = idx & 31;
    float4 v = ((const float4*)f)[idx];
    float4 m = ((const float4*)mean)[soff4 + c4];
    float4 r = ((const float4*)rstd)[soff4 + c4];
    float4 o;
    o.x = (v.x - m.x) * r.x;
    o.y = (v.y - m.y) * r.y;
    o.z = (v.z - m.z) * r.z;
    o.w = (v.w - m.w) * r.w;
    ((float4*)o_base)[idx] = o;
}

// ---------------- host launcher ----------------

static void* sym_addr(const void* symbol) {
    void* p = nullptr;
    cudaGetSymbolAddress(&p, symbol);
    return p;
}

extern "C" void kernel_launch(void* const* d_in, const int* in_sizes, int n_in,
                              void* d_out, int out_size) {
    const float* feat1   = (const float*)d_in[0];
    const float* feat2   = (const float*)d_in[1];
    const int*   src1    = (const int*)d_in[2];
    const int*   dst1    = (const int*)d_in[3];
    const int*   src2    = (const int*)d_in[4];
    const int*   dst2    = (const int*)d_in[5];
    const float* weights = (const float*)d_in[6];
    const float* biases  = (const float*)d_in[7];
    const int E1 = in_sizes[2];
    const int E2 = in_sizes[4];
    const int N = NNODES;
    const int L = in_sizes[7] / DFEAT;

    float* p_h1    = (float*)sym_addr(g_h1);
    float* p_h2    = (float*)sym_addr(g_h2);
    float* p_f1    = (float*)sym_addr(g_feat1);
    float* p_f2    = (float*)sym_addr(g_feat2);
    float* p_wp    = (float*)sym_addr(g_wp);
    int*   p_col1  = (int*)sym_addr(g_col1);
    int*   p_col2  = (int*)sym_addr(g_col2);
    int*   p_deg1  = (int*)sym_addr(g_deg1);
    int*   p_deg2  = (int*)sym_addr(g_deg2);
    int*   p_rp1   = (int*)sym_addr(g_rowptr1);
    int*   p_rp2   = (int*)sym_addr(g_rowptr2);
    int*   p_cur1  = (int*)sym_addr(g_cursor1);
    int*   p_cur2  = (int*)sym_addr(g_cursor2);
    float* p_norm1 = (float*)sym_addr(g_norm1);
    float* p_norm2 = (float*)sym_addr(g_norm2);
    double* p_sum  = (double*)sym_addr(g_sum);
    double* p_sq   = (double*)sym_addr(g_sumsq);
    float* p_mean  = (float*)sym_addr(g_mean);
    float* p_rstd  = (float*)sym_addr(g_rstd);

    // 1. zero deg + stats
    zero_kernel<<<(N + 255) / 256, 256>>>(p_deg1, p_deg2, p_sum, p_sq, N);

    // 2. degree histograms (both graphs)
    {
        int Emax = E1 > E2 ? E1 : E2;
        dim3 grid((Emax + 255) / 256, 2);
        hist2_kernel<<<grid, 256>>>(dst1, p_deg1, E1, dst2, p_deg2, E2);
    }

    // 3. scans (one block per graph) -> rowptr/cursor/norm
    scan2_kernel<<<2, 1024>>>(p_deg1, p_rp1, p_cur1, p_norm1,
                              p_deg2, p_rp2, p_cur2, p_norm2, N);

    // 4. CSR fill (both graphs)
    {
        int Emax = E1 > E2 ? E1 : E2;
        dim3 grid((Emax + 255) / 256, 2);
        fill2_kernel<<<grid, 256>>>(src1, dst1, p_cur1, p_col1, E1,
                                    src2, dst2, p_cur2, p_col2, E2);
    }

    // 5. W' = (1-beta)I + beta W per layer
    {
        dim3 grid((DFEAT * DFEAT + 255) / 256, L);
        wprime_kernel<<<grid, 256>>>(weights, p_wp);
    }

    // 6. GCNII layers (both graphs per launch)
    const dim3 agg_grid((N * 32 + 255) / 256, 2);
    const dim3 gemm_grid((N + 127) / 128, 2);
    const float* cur1 = feat1;
    const float* cur2 = feat2;
    for (int l = 0; l < L; l++) {
        const float* Wl = p_wp + (size_t)l * DFEAT * DFEAT;
        const float* bl = biases + (size_t)l * DFEAT;

        aggregate2_kernel<<<agg_grid, 256>>>(cur1, feat1, p_norm1, p_rp1, p_col1, p_h1,
                                             cur2, feat2, p_norm2, p_rp2, p_col2, p_h2, N);
        gemm2_kernel<<<gemm_grid, 256>>>(p_h1, p_f1, p_h2, p_f2, Wl, bl, N);
        cur1 = p_f1;
        cur2 = p_f2;
    }

    // 7. column stats (both graphs)
    {
        dim3 grid(256, 2);
        colstats2_kernel<<<grid, 256>>>(p_f1, p_f2, p_sum, p_sq, N);
    }

    // 8. mean / rstd
    finalize_kernel<<<1, 256>>>(p_sum, p_sq, p_mean, p_rstd, N);

    // 9. standardized output: [h1 | h2]
    {
        dim3 grid((N * 32 + 255) / 256, 2);
        writeout2_kernel<<<grid, 256>>>(p_f1, p_f2, p_mean, p_rstd, (float*)d_out, N);
    }
}

// round 3
// speedup vs baseline: 1.3442x; 1.0615x over previous
#include <cuda_runtime.h>
#include <cuda_bf16.h>
#include <math.h>
#include <stdint.h>

// Problem constants (fixed by reference)
#define NNODES 100000
#define DFEAT  128
#define EMAX   1600000
#define ALPHA_C 0.1f
#define LMAX   8

// ---------------- scratch (device globals; no allocation allowed) ----------------
__device__ float  g_h1[NNODES * DFEAT];
__device__ float  g_h2[NNODES * DFEAT];
__device__ float  g_feat1[NNODES * DFEAT];
__device__ float  g_feat2[NNODES * DFEAT];
__device__ float2 g_wp2[LMAX * DFEAT * DFEAT];   // [l][n][k] = (hi, lo) of W'[k][n]
__device__ int    g_col1[EMAX];
__device__ int    g_col2[EMAX];
__device__ int    g_deg1[NNODES];
__device__ int    g_deg2[NNODES];
__device__ int    g_rowptr1[NNODES + 1];
__device__ int    g_rowptr2[NNODES + 1];
__device__ int    g_cursor1[NNODES];
__device__ int    g_cursor2[NNODES];
__device__ float  g_norm1[NNODES];
__device__ float  g_norm2[NNODES];
__device__ double g_sum[256];    // [graph*128 + col]
__device__ double g_sumsq[256];
__device__ float  g_mean[256];
__device__ float  g_rstd[256];

// ---------------- kernels ----------------

__global__ void zero_kernel(int* d1, int* d2, double* s, double* s2, int n) {
    int i = blockIdx.x * blockDim.x + threadIdx.x;
    if (i < n) { d1[i] = 0; d2[i] = 0; }
    if (i < 256) { s[i] = 0.0; s2[i] = 0.0; }
}

__global__ void hist2_kernel(const int* __restrict__ dstA, int* __restrict__ degA, int EA,
                             const int* __restrict__ dstB, int* __restrict__ degB, int EB) {
    const int* dst = blockIdx.y ? dstB : dstA;
    int*       deg = blockIdx.y ? degB : degA;
    int        E   = blockIdx.y ? EB : EA;
    int i = blockIdx.x * blockDim.x + threadIdx.x;
    if (i < E) atomicAdd(&deg[dst[i]], 1);
}

// fast single-block-per-graph scan: 1024 threads, 4 elems/thread, warp-shuffle scan.
__global__ __launch_bounds__(1024) void scan2_kernel(
    const int* __restrict__ degA, int* __restrict__ rpA, int* __restrict__ curA, float* __restrict__ normA,
    const int* __restrict__ degB, int* __restrict__ rpB, int* __restrict__ curB, float* __restrict__ normB,
    int n)
{
    const int* deg  = blockIdx.x ? degB  : degA;
    int*       rp   = blockIdx.x ? rpB   : rpA;
    int*       cur  = blockIdx.x ? curB  : curA;
    float*     norm = blockIdx.x ? normB : normA;

    __shared__ int wsum[32];
    __shared__ int s_carry;
    int tid = threadIdx.x, lane = tid & 31, wid = tid >> 5;
    if (tid == 0) s_carry = 0;
    __syncthreads();

    for (int base = 0; base < n; base += 4096) {
        int idx = base + tid * 4;
        int v0 = (idx + 0 < n) ? deg[idx + 0] : 0;
        int v1 = (idx + 1 < n) ? deg[idx + 1] : 0;
        int v2 = (idx + 2 < n) ? deg[idx + 2] : 0;
        int v3 = (idx + 3 < n) ? deg[idx + 3] : 0;
        int p0 = v0, p1 = p0 + v1, p2 = p1 + v2, p3 = p2 + v3;
        int tot = p3;
        #pragma unroll
        for (int off = 1; off < 32; off <<= 1) {
            int t = __shfl_up_sync(0xFFFFFFFFu, tot, off);
            if (lane >= off) tot += t;
        }
        if (lane == 31) wsum[wid] = tot;
        __syncthreads();
        if (wid == 0) {
            int w = wsum[lane];
            #pragma unroll
            for (int off = 1; off < 32; off <<= 1) {
                int t = __shfl_up_sync(0xFFFFFFFFu, w, off);
                if (lane >= off) w += t;
            }
            wsum[lane] = w;
        }
        __syncthreads();
        int carry = s_carry;
        int excl = carry + (wid ? wsum[wid - 1] : 0) + (tot - p3);
        if (idx + 0 < n) { rp[idx + 0] = excl;      cur[idx + 0] = excl;      norm[idx + 0] = rsqrtf(fmaxf((float)v0, 1.f)); }
        if (idx + 1 < n) { rp[idx + 1] = excl + p0; cur[idx + 1] = excl + p0; norm[idx + 1] = rsqrtf(fmaxf((float)v1, 1.f)); }
        if (idx + 2 < n) { rp[idx + 2] = excl + p1; cur[idx + 2] = excl + p1; norm[idx + 2] = rsqrtf(fmaxf((float)v2, 1.f)); }
        if (idx + 3 < n) { rp[idx + 3] = excl + p2; cur[idx + 3] = excl + p2; norm[idx + 3] = rsqrtf(fmaxf((float)v3, 1.f)); }
        __syncthreads();
        if (tid == 0) s_carry = carry + wsum[31];
        __syncthreads();
    }
    if (tid == 0) rp[n] = s_carry;
}

__global__ void fill2_kernel(const int* __restrict__ srcA, const int* __restrict__ dstA,
                             int* __restrict__ curA, int* __restrict__ colA, int EA,
                             const int* __restrict__ srcB, const int* __restrict__ dstB,
                             int* __restrict__ curB, int* __restrict__ colB, int EB) {
    const int* src = blockIdx.y ? srcB : srcA;
    const int* dst = blockIdx.y ? dstB : dstA;
    int* cursor    = blockIdx.y ? curB : curA;
    int* col       = blockIdx.y ? colB : colA;
    int  E         = blockIdx.y ? EB : EA;
    int i = blockIdx.x * blockDim.x + threadIdx.x;
    if (i < E) {
        int d = dst[i];
        int p = atomicAdd(&cursor[d], 1);
        col[p] = src[i];
    }
}

// W' = (1-beta)*I + beta*W, split into tf32 hi/lo, stored transposed [n][k]
__global__ void wprime2_kernel(const float* __restrict__ W, float2* __restrict__ Wp2) {
    int l = blockIdx.y;
    int i = blockIdx.x * blockDim.x + threadIdx.x;   // 0..16383
    if (i >= DFEAT * DFEAT) return;
    float beta = logf(1.0f / (float)(l + 1) + 1.0f); // LAMBDA = 1
    int n = i >> 7, k = i & 127;
    float v = beta * W[l * DFEAT * DFEAT + k * DFEAT + n];
    if (k == n) v += 1.0f - beta;
    float hi = __uint_as_float(__float_as_uint(v) & 0xFFFFE000u);
    float lo = v - hi;
    Wp2[l * DFEAT * DFEAT + i] = make_float2(hi, lo);
}

// warp-per-row aggregation, both graphs (gridDim.y = 2):
// h[i] = (1-ALPHA)*norm[i]*sum_{e in row i} norm[src]*feat[src] + ALPHA*feat0[i]
__global__ __launch_bounds__(256) void aggregate2_kernel(
    const float* __restrict__ fA, const float* __restrict__ f0A, const float* __restrict__ nmA,
    const int* __restrict__ rpA, const int* __restrict__ colA, float* __restrict__ hA,
    const float* __restrict__ fB, const float* __restrict__ f0B, const float* __restrict__ nmB,
    const int* __restrict__ rpB, const int* __restrict__ colB, float* __restrict__ hB,
    int n)
{
    const float* feat  = blockIdx.y ? fB  : fA;
    const float* feat0 = blockIdx.y ? f0B : f0A;
    const float* norm  = blockIdx.y ? nmB : nmA;
    const int*   rowptr= blockIdx.y ? rpB : rpA;
    const int*   col   = blockIdx.y ? colB: colA;
    float*       h     = blockIdx.y ? hB  : hA;

    int warp = (blockIdx.x * blockDim.x + threadIdx.x) >> 5;
    int lane = threadIdx.x & 31;
    if (warp >= n) return;
    int e0 = __ldg(&rowptr[warp]);
    int e1 = __ldg(&rowptr[warp + 1]);
    float4 acc = make_float4(0.f, 0.f, 0.f, 0.f);
    int e = e0;
    for (; e + 1 < e1; e += 2) {
        int s0 = __ldg(&col[e]);
        int s1 = __ldg(&col[e + 1]);
        float n0 = __ldg(&norm[s0]);
        float n1 = __ldg(&norm[s1]);
        float4 f0 = __ldg((const float4*)&feat[s0 * DFEAT + lane * 4]);
        float4 f1 = __ldg((const float4*)&feat[s1 * DFEAT + lane * 4]);
        acc.x += n0 * f0.x + n1 * f1.x;
        acc.y += n0 * f0.y + n1 * f1.y;
        acc.z += n0 * f0.z + n1 * f1.z;
        acc.w += n0 * f0.w + n1 * f1.w;
    }
    if (e < e1) {
        int s0 = __ldg(&col[e]);
        float n0 = __ldg(&norm[s0]);
        float4 f0 = __ldg((const float4*)&feat[s0 * DFEAT + lane * 4]);
        acc.x += n0 * f0.x; acc.y += n0 * f0.y;
        acc.z += n0 * f0.z; acc.w += n0 * f0.w;
    }
    float scale = (1.0f - ALPHA_C) * __ldg(&norm[warp]);
    float4 f0v = __ldg((const float4*)&feat0[warp * DFEAT + lane * 4]);
    float4 o;
    o.x = scale * acc.x + ALPHA_C * f0v.x;
    o.y = scale * acc.y + ALPHA_C * f0v.y;
    o.z = scale * acc.z + ALPHA_C * f0v.z;
    o.w = scale * acc.w + ALPHA_C * f0v.w;
    *(float4*)&h[warp * DFEAT + lane * 4] = o;
}

// ---------------- 3xTF32 tensor-core GEMM ----------------
// feat_out = relu(h @ W' + bias)  via mma.sync m16n8k8 tf32 with hi/lo split.
// Block tile 128x128, BK=16, 8 warps, warp tile 64x32.

__device__ __forceinline__ void mma_tf32(float c[4], const uint32_t a[4],
                                         uint32_t b0, uint32_t b1) {
    asm volatile(
        "mma.sync.aligned.m16n8k8.row.col.f32.tf32.tf32.f32 "
        "{%0,%1,%2,%3}, {%4,%5,%6,%7}, {%8,%9}, {%0,%1,%2,%3};\n"
        : "+f"(c[0]), "+f"(c[1]), "+f"(c[2]), "+f"(c[3])
        : "r"(a[0]), "r"(a[1]), "r"(a[2]), "r"(a[3]), "r"(b0), "r"(b1));
}

#define HS_STRIDE 18   // float2 stride per row (16 + 2 pad)

__global__ __launch_bounds__(256, 2) void gemm2_tc_kernel(
    const float* __restrict__ hA, float* __restrict__ outA,
    const float* __restrict__ hB, float* __restrict__ outB,
    const float2* __restrict__ Wp2, const float* __restrict__ bias, int nrows)
{
    const float* h   = blockIdx.y ? hB  : hA;
    float*       out = blockIdx.y ? outB : outA;

    __shared__ float2 Hs[128 * HS_STRIDE];  // [row][k] (hi,lo)
    __shared__ float2 Ws[128 * HS_STRIDE];  // [n][k]   (hi,lo)

    const int tid = threadIdx.x;
    const int wid = tid >> 5;
    const int lane = tid & 31;
    const int g = lane >> 2;      // 0..7
    const int tg = lane & 3;      // 0..3
    const int warpM = wid & 1;    // 2 over M: 64 rows each
    const int warpN = wid >> 1;   // 4 over N: 32 cols each
    const int M0w = warpM * 64;
    const int N0w = warpN * 32;
    const int blockRow = blockIdx.x * 128;

    float c[4][4][4];   // [mt][nt][frag]
    #pragma unroll
    for (int mt = 0; mt < 4; mt++)
        #pragma unroll
        for (int nt = 0; nt < 4; nt++)
            #pragma unroll
            for (int q = 0; q < 4; q++) c[mt][nt][q] = 0.f;

    for (int stage = 0; stage < 8; stage++) {
        const int ks0 = stage * 16;
        // ---- fill Hs: 128 rows x 16 k (512 float4 of h), split hi/lo ----
        #pragma unroll
        for (int it = 0; it < 2; it++) {
            int f = tid + it * 256;          // 0..511
            int row = f >> 2;
            int kq = f & 3;
            int grow = blockRow + row;
            float4 v = make_float4(0.f, 0.f, 0.f, 0.f);
            if (grow < nrows)
                v = *(const float4*)&h[grow * DFEAT + ks0 + kq * 4];
            float2* dst = &Hs[row * HS_STRIDE + kq * 4];
            float hx = __uint_as_float(__float_as_uint(v.x) & 0xFFFFE000u);
            float hy = __uint_as_float(__float_as_uint(v.y) & 0xFFFFE000u);
            float hz = __uint_as_float(__float_as_uint(v.z) & 0xFFFFE000u);
            float hw = __uint_as_float(__float_as_uint(v.w) & 0xFFFFE000u);
            ((float4*)dst)[0] = make_float4(hx, v.x - hx, hy, v.y - hy);
            ((float4*)dst)[1] = make_float4(hz, v.z - hz, hw, v.w - hw);
        }
        // ---- fill Ws: copy pre-split Wp2 [n][k]: 1024 float4 ----
        #pragma unroll
        for (int it = 0; it < 4; it++) {
            int f = tid + it * 256;          // 0..1023
            int n = f >> 3;
            int q = f & 7;                   // 8 float4 per n-row (16 float2)
            float4 v = *(const float4*)&Wp2[n * DFEAT + ks0 + q * 2];
            *(float4*)&Ws[n * HS_STRIDE + q * 2] = v;
        }
        __syncthreads();

        #pragma unroll
        for (int ks = 0; ks < 2; ks++) {
            const int K0 = ks * 8;
            // load A frags (hi & lo) for 4 M-tiles
            uint32_t ah[4][4], al[4][4];
            #pragma unroll
            for (int mt = 0; mt < 4; mt++) {
                int base = (M0w + mt * 16 + g) * HS_STRIDE + K0 + tg;
                float2 v0 = Hs[base];                 // a0: (row g,   k tg)
                float2 v1 = Hs[base + 8 * HS_STRIDE]; // a1: (row g+8, k tg)
                float2 v2 = Hs[base + 4];             // a2: (row g,   k tg+4)
                float2 v3 = Hs[base + 8 * HS_STRIDE + 4];
                ah[mt][0] = __float_as_uint(v0.x); al[mt][0] = __float_as_uint(v0.y);
                ah[mt][1] = __float_as_uint(v1.x); al[mt][1] = __float_as_uint(v1.y);
                ah[mt][2] = __float_as_uint(v2.x); al[mt][2] = __float_as_uint(v2.y);
                ah[mt][3] = __float_as_uint(v3.x); al[mt][3] = __float_as_uint(v3.y);
            }
            // load B frags for 4 N-tiles
            uint32_t bh[4][2], bl[4][2];
            #pragma unroll
            for (int nt = 0; nt < 4; nt++) {
                int base = (N0w + nt * 8 + g) * HS_STRIDE + K0 + tg;
                float2 v0 = Ws[base];      // b0: (k tg,   n g)
                float2 v1 = Ws[base + 4];  // b1: (k tg+4, n g)
                bh[nt][0] = __float_as_uint(v0.x); bl[nt][0] = __float_as_uint(v0.y);
                bh[nt][1] = __float_as_uint(v1.x); bl[nt][1] = __float_as_uint(v1.y);
            }
            // 3xTF32 mma
            #pragma unroll
            for (int mt = 0; mt < 4; mt++)
                #pragma unroll
                for (int nt = 0; nt < 4; nt++) {
                    mma_tf32(c[mt][nt], ah[mt], bh[nt][0], bh[nt][1]);
                    mma_tf32(c[mt][nt], ah[mt], bl[nt][0], bl[nt][1]);
                    mma_tf32(c[mt][nt], al[mt], bh[nt][0], bh[nt][1]);
                }
        }
        __syncthreads();
    }

    // ---- epilogue: relu(c + bias) ----
    #pragma unroll
    for (int mt = 0; mt < 4; mt++) {
        int row0 = blockRow + M0w + mt * 16 + g;
        int row1 = row0 + 8;
        #pragma unroll
        for (int nt = 0; nt < 4; nt++) {
            int colj = N0w + nt * 8 + 2 * tg;
            float2 bv = *(const float2*)&bias[colj];
            if (row0 < nrows) {
                float2 o0;
                o0.x = fmaxf(c[mt][nt][0] + bv.x, 0.f);
                o0.y = fmaxf(c[mt][nt][1] + bv.y, 0.f);
                *(float2*)&out[row0 * DFEAT + colj] = o0;
            }
            if (row1 < nrows) {
                float2 o1;
                o1.x = fmaxf(c[mt][nt][2] + bv.x, 0.f);
                o1.y = fmaxf(c[mt][nt][3] + bv.y, 0.f);
                *(float2*)&out[row1 * DFEAT + colj] = o1;
            }
        }
    }
}

// per-column sums / sumsq (double accumulation), both graphs (gridDim.y = 2)
__global__ void colstats2_kernel(const float* __restrict__ fA, const float* __restrict__ fB,
                                 double* __restrict__ sum, double* __restrict__ sumsq, int n) {
    const float* f = blockIdx.y ? fB : fA;
    int soff = blockIdx.y * 128;
    __shared__ double ss[256];
    __shared__ double ss2[256];
    int col = threadIdx.x & 127;
    int half = threadIdx.x >> 7;
    double s = 0.0, s2 = 0.0;
    for (int r = blockIdx.x * 2 + half; r < n; r += gridDim.x * 2) {
        float v = f[r * DFEAT + col];
        s += (double)v;
        s2 += (double)v * (double)v;
    }
    ss[threadIdx.x] = s;
    ss2[threadIdx.x] = s2;
    __syncthreads();
    if (half == 0) {
        atomicAdd(&sum[soff + col], ss[threadIdx.x] + ss[threadIdx.x + 128]);
        atomicAdd(&sumsq[soff + col], ss2[threadIdx.x] + ss2[threadIdx.x + 128]);
    }
}

__global__ void finalize_kernel(const double* __restrict__ sum, const double* __restrict__ sumsq,
                                float* __restrict__ mean, float* __restrict__ rstd, int n) {
    int i = threadIdx.x;
    if (i < 256) {
        double s = sum[i], s2 = sumsq[i];
        double m = s / (double)n;
        double var = (s2 - s * s / (double)n) / (double)(n - 1);
        double sd = sqrt(fmax(var, 0.0));
        sd = fmax(sd, 1e-12);
        mean[i] = (float)m;
        rstd[i] = (float)(1.0 / sd);
    }
}

__global__ void writeout2_kernel(const float* __restrict__ fA, const float* __restrict__ fB,
                                 const float* __restrict__ mean, const float* __restrict__ rstd,
                                 float* __restrict__ out, int n) {
    const float* f = blockIdx.y ? fB : fA;
    int soff4 = blockIdx.y * 32;
    float* o_base = out + (size_t)blockIdx.y * n * DFEAT;
    int idx = blockIdx.x * blockDim.x + threadIdx.x;  // over n*32 float4s
    if (idx >= n * 32) return;
    int c4 = idx & 31;
    float4 v = ((const float4*)f)[idx];
    float4 m = ((const float4*)mean)[soff4 + c4];
    float4 r = ((const float4*)rstd)[soff4 + c4];
    float4 o;
    o.x = (v.x - m.x) * r.x;
    o.y = (v.y - m.y) * r.y;
    o.z = (v.z - m.z) * r.z;
    o.w = (v.w - m.w) * r.w;
    ((float4*)o_base)[idx] = o;
}

// ---------------- host launcher ----------------

static void* sym_addr(const void* symbol) {
    void* p = nullptr;
    cudaGetSymbolAddress(&p, symbol);
    return p;
}

extern "C" void kernel_launch(void* const* d_in, const int* in_sizes, int n_in,
                              void* d_out, int out_size) {
    const float* feat1   = (const float*)d_in[0];
    const float* feat2   = (const float*)d_in[1];
    const int*   src1    = (const int*)d_in[2];
    const int*   dst1    = (const int*)d_in[3];
    const int*   src2    = (const int*)d_in[4];
    const int*   dst2    = (const int*)d_in[5];
    const float* weights = (const float*)d_in[6];
    const float* biases  = (const float*)d_in[7];
    const int E1 = in_sizes[2];
    const int E2 = in_sizes[4];
    const int N = NNODES;
    const int L = in_sizes[7] / DFEAT;

    float* p_h1    = (float*)sym_addr(g_h1);
    float* p_h2    = (float*)sym_addr(g_h2);
    float* p_f1    = (float*)sym_addr(g_feat1);
    float* p_f2    = (float*)sym_addr(g_feat2);
    float2* p_wp2  = (float2*)sym_addr(g_wp2);
    int*   p_col1  = (int*)sym_addr(g_col1);
    int*   p_col2  = (int*)sym_addr(g_col2);
    int*   p_deg1  = (int*)sym_addr(g_deg1);
    int*   p_deg2  = (int*)sym_addr(g_deg2);
    int*   p_rp1   = (int*)sym_addr(g_rowptr1);
    int*   p_rp2   = (int*)sym_addr(g_rowptr2);
    int*   p_cur1  = (int*)sym_addr(g_cursor1);
    int*   p_cur2  = (int*)sym_addr(g_cursor2);
    float* p_norm1 = (float*)sym_addr(g_norm1);
    float* p_norm2 = (float*)sym_addr(g_norm2);
    double* p_sum  = (double*)sym_addr(g_sum);
    double* p_sq   = (double*)sym_addr(g_sumsq);
    float* p_mean  = (float*)sym_addr(g_mean);
    float* p_rstd  = (float*)sym_addr(g_rstd);

    // 1. zero deg + stats
    zero_kernel<<<(N + 255) / 256, 256>>>(p_deg1, p_deg2, p_sum, p_sq, N);

    // 2. degree histograms (both graphs)
    {
        int Emax = E1 > E2 ? E1 : E2;
        dim3 grid((Emax + 255) / 256, 2);
        hist2_kernel<<<grid, 256>>>(dst1, p_deg1, E1, dst2, p_deg2, E2);
    }

    // 3. scans (one block per graph)
    scan2_kernel<<<2, 1024>>>(p_deg1, p_rp1, p_cur1, p_norm1,
                              p_deg2, p_rp2, p_cur2, p_norm2, N);

    // 4. CSR fill (both graphs)
    {
        int Emax = E1 > E2 ? E1 : E2;
        dim3 grid((Emax + 255) / 256, 2);
        fill2_kernel<<<grid, 256>>>(src1, dst1, p_cur1, p_col1, E1,
                                    src2, dst2, p_cur2, p_col2, E2);
    }

    // 5. W' split+transposed per layer
    {
        dim3 grid((DFEAT * DFEAT + 255) / 256, L);
        wprime2_kernel<<<grid, 256>>>(weights, p_wp2);
    }

    // 6. GCNII layers (both graphs per launch)
    const dim3 agg_grid((N * 32 + 255) / 256, 2);
    const dim3 gemm_grid((N + 127) / 128, 2);
    const float* cur1 = feat1;
    const float* cur2 = feat2;
    for (int l = 0; l < L; l++) {
        const float2* Wl = p_wp2 + (size_t)l * DFEAT * DFEAT;
        const float* bl = biases + (size_t)l * DFEAT;

        aggregate2_kernel<<<agg_grid, 256>>>(cur1, feat1, p_norm1, p_rp1, p_col1, p_h1,
                                             cur2, feat2, p_norm2, p_rp2, p_col2, p_h2, N);
        gemm2_tc_kernel<<<gemm_grid, 256>>>(p_h1, p_f1, p_h2, p_f2, Wl, bl, N);
        cur1 = p_f1;
        cur2 = p_f2;
    }

    // 7. column stats (both graphs)
    {
        dim3 grid(256, 2);
        colstats2_kernel<<<grid, 256>>>(p_f1, p_f2, p_sum, p_sq, N);
    }

    // 8. mean / rstd
    finalize_kernel<<<1, 256>>>(p_sum, p_sq, p_mean, p_rstd, N);

    // 9. standardized output: [h1 | h2]
    {
        dim3 grid((N * 32 + 255) / 256, 2);
        writeout2_kernel<<<grid, 256>>>(p_f1, p_f2, p_mean, p_rstd, (float*)d_out, N);
    }
}